// round 4
// baseline (speedup 1.0000x reference)
#include <cuda_runtime.h>

namespace {
constexpr int N_NODES = 100000;
constexpr int HID     = 64;
constexpr int N_LAYERS = 4;
constexpr int N_EDGES = 800000;
constexpr float EPS = 1e-5f;
}

// Scratch buffers (no cudaMalloc allowed)
__device__ float g_m  [(size_t)N_NODES * HID];
__device__ float g_agg[(size_t)N_NODES * HID];
__device__ float g_h  [(size_t)N_NODES * HID];

// ---- packed f32x2 helpers (double is just a 64-bit carrier of two f32) ----
__device__ __forceinline__ double ffma2(double a, double b, double c) {
    double d; asm("fma.rn.f32x2 %0,%1,%2,%3;" : "=d"(d) : "d"(a), "d"(b), "d"(c)); return d;
}
__device__ __forceinline__ double fadd2(double a, double b) {
    double d; asm("add.rn.f32x2 %0,%1,%2;" : "=d"(d) : "d"(a), "d"(b)); return d;
}
__device__ __forceinline__ double fmul2(double a, double b) {
    double d; asm("mul.rn.f32x2 %0,%1,%2;" : "=d"(d) : "d"(a), "d"(b)); return d;
}
__device__ __forceinline__ float flo(double d) { return __int_as_float(__double2loint(d)); }
__device__ __forceinline__ float fhi(double d) { return __int_as_float(__double2hiint(d)); }
__device__ __forceinline__ double fpack(float lo, float hi) {
    return __hiloint2double(__float_as_int(hi), __float_as_int(lo));
}

// =====================================================================
// K1: m = relu(h @ Wc^T); also zero agg rows (stream-ordered before K2)
// =====================================================================
__global__ void __launch_bounds__(128) k_conv_gemm(
    const float* __restrict__ h, const float* __restrict__ W,
    float* __restrict__ m, float* __restrict__ agg)
{
    __shared__ __align__(16) float ws[HID * HID];   // row-major W[o][k]
    for (int i = threadIdx.x; i < HID * HID; i += 128) ws[i] = W[i];
    __syncthreads();

    int node = blockIdx.x * 128 + threadIdx.x;
    if (node >= N_NODES) return;

    // h row as 32 packed k-pairs
    double hv[32];
    const double2* hrow = reinterpret_cast<const double2*>(h + (size_t)node * HID);
#pragma unroll
    for (int i = 0; i < 16; i++) {
        double2 t = __ldg(hrow + i);
        hv[2 * i] = t.x; hv[2 * i + 1] = t.y;
    }

    float4* mrow = reinterpret_cast<float4*>(m + (size_t)node * HID);
    float4* arow = reinterpret_cast<float4*>(agg + (size_t)node * HID);
    const float4 z4 = make_float4(0.f, 0.f, 0.f, 0.f);

#pragma unroll
    for (int jb = 0; jb < 4; jb++) {
        float o[16];
#pragma unroll
        for (int jj = 0; jj < 16; jj++) {
            const double2* wrow =
                reinterpret_cast<const double2*>(ws + (jb * 16 + jj) * HID);
            double a = 0.0, b = 0.0;
#pragma unroll
            for (int kq = 0; kq < 16; kq += 2) {
                double2 w0 = wrow[kq];
                a = ffma2(hv[2 * kq],     w0.x, a);
                b = ffma2(hv[2 * kq + 1], w0.y, b);
                double2 w1 = wrow[kq + 1];
                a = ffma2(hv[2 * kq + 2], w1.x, a);
                b = ffma2(hv[2 * kq + 3], w1.y, b);
            }
            double s = fadd2(a, b);
            float v = flo(s) + fhi(s);
            o[jj] = fmaxf(v, 0.f);
        }
#pragma unroll
        for (int q = 0; q < 4; q++) {
            mrow[jb * 4 + q] = make_float4(o[4*q], o[4*q+1], o[4*q+2], o[4*q+3]);
            arow[jb * 4 + q] = z4;
        }
    }
}

// =====================================================================
// K2: agg[row[e]] += m[col[e]]   (16 lanes per edge, float4 vector red)
// =====================================================================
__global__ void __launch_bounds__(256) k_scatter(
    const float4* __restrict__ m, const int* __restrict__ row,
    const int* __restrict__ col, float* __restrict__ agg)
{
    int gid = blockIdx.x * 256 + threadIdx.x;
    int e = gid >> 4;
    if (e >= N_EDGES) return;
    int l = gid & 15;
    int c = __ldg(col + e);
    int r = __ldg(row + e);
    float4 v = __ldg(m + (size_t)c * 16 + l);
    float* dst = agg + (size_t)r * HID + l * 4;
    asm volatile("red.global.add.v4.f32 [%0], {%1,%2,%3,%4};"
                 :: "l"(dst), "f"(v.x), "f"(v.y), "f"(v.z), "f"(v.w)
                 : "memory");
}

// =====================================================================
// K3: h' = rmsnorm(h+agg, cnw); y = relu(h' @ Wh^T); out = rmsnorm(h'+y, hnw)
// =====================================================================
__global__ void __launch_bounds__(128) k_norm_hid(
    const float* __restrict__ h, const float* __restrict__ agg,
    const float* __restrict__ W, const float* __restrict__ cnw,
    const float* __restrict__ hnw, float* __restrict__ out)
{
    __shared__ __align__(16) float ws[HID * HID];
    __shared__ __align__(16) float cn[HID];
    __shared__ float hn[HID];
    for (int i = threadIdx.x; i < HID * HID; i += 128) ws[i] = W[i];
    if (threadIdx.x < HID) {
        cn[threadIdx.x] = cnw[threadIdx.x];
        hn[threadIdx.x] = hnw[threadIdx.x];
    }
    __syncthreads();

    int node = blockIdx.x * 128 + threadIdx.x;
    if (node >= N_NODES) return;

    const double2* hrow = reinterpret_cast<const double2*>(h + (size_t)node * HID);
    const double2* arow = reinterpret_cast<const double2*>(agg + (size_t)node * HID);

    double hv[32];
    double sq = 0.0;
#pragma unroll
    for (int i = 0; i < 16; i++) {
        double2 a = __ldg(hrow + i);
        double2 b = __ldg(arow + i);
        double t0 = fadd2(a.x, b.x);
        double t1 = fadd2(a.y, b.y);
        hv[2 * i] = t0; hv[2 * i + 1] = t1;
        sq = ffma2(t0, t0, sq);
        sq = ffma2(t1, t1, sq);
    }
    float ssq = flo(sq) + fhi(sq);
    float inv1 = rsqrtf(ssq * (1.f / HID) + EPS);
    double inv1p = fpack(inv1, inv1);

    const double2* cnp = reinterpret_cast<const double2*>(cn);
#pragma unroll
    for (int i = 0; i < 16; i++) {
        double2 c = cnp[i];
        hv[2 * i]     = fmul2(fmul2(hv[2 * i],     inv1p), c.x);
        hv[2 * i + 1] = fmul2(fmul2(hv[2 * i + 1], inv1p), c.y);
    }

    // y = h' @ Wh^T ; z = h' + relu(y)
    float zf[64];
    float sq2 = 0.f;
#pragma unroll
    for (int jb = 0; jb < 4; jb++) {
#pragma unroll
        for (int jj = 0; jj < 16; jj++) {
            int o = jb * 16 + jj;
            const double2* wrow = reinterpret_cast<const double2*>(ws + o * HID);
            double a = 0.0, b = 0.0;
#pragma unroll
            for (int kq = 0; kq < 16; kq += 2) {
                double2 w0 = wrow[kq];
                a = ffma2(hv[2 * kq],     w0.x, a);
                b = ffma2(hv[2 * kq + 1], w0.y, b);
                double2 w1 = wrow[kq + 1];
                a = ffma2(hv[2 * kq + 2], w1.x, a);
                b = ffma2(hv[2 * kq + 3], w1.y, b);
            }
            double s = fadd2(a, b);
            float y = flo(s) + fhi(s);
            float hp = (o & 1) ? fhi(hv[o >> 1]) : flo(hv[o >> 1]);
            float z = hp + fmaxf(y, 0.f);
            zf[o] = z;
            sq2 = fmaf(z, z, sq2);
        }
    }
    float inv2 = rsqrtf(sq2 * (1.f / HID) + EPS);

    float4* orow = reinterpret_cast<float4*>(out + (size_t)node * HID);
#pragma unroll
    for (int q = 0; q < 16; q++) {
        orow[q] = make_float4(zf[4*q]   * inv2 * hn[4*q],
                              zf[4*q+1] * inv2 * hn[4*q+1],
                              zf[4*q+2] * inv2 * hn[4*q+2],
                              zf[4*q+3] * inv2 * hn[4*q+3]);
    }
}

// =====================================================================
extern "C" void kernel_launch(void* const* d_in, const int* in_sizes, int n_in,
                              void* d_out, int out_size)
{
    const float* x         = (const float*)d_in[0];
    const float* conv_w    = (const float*)d_in[1];
    const float* conv_norm = (const float*)d_in[2];
    const float* hid_w     = (const float*)d_in[3];
    const float* hid_norm  = (const float*)d_in[4];
    const int*   row       = (const int*)d_in[5];
    const int*   col       = (const int*)d_in[6];
    float*       out       = (float*)d_out;

    float *mp = nullptr, *ap = nullptr, *hp = nullptr;
    cudaGetSymbolAddress((void**)&mp, g_m);
    cudaGetSymbolAddress((void**)&ap, g_agg);
    cudaGetSymbolAddress((void**)&hp, g_h);

    const int NB = (N_NODES + 127) / 128;
    const int EB = (N_EDGES * 16) / 256;  // exact: 800000*16 = 12.8M, /256 = 50000

    for (int l = 0; l < N_LAYERS; l++) {
        const float* hsrc = (l == 0) ? x : hp;
        float* hdst = (l == N_LAYERS - 1) ? out : hp;
        k_conv_gemm<<<NB, 128>>>(hsrc, conv_w + l * HID * HID, mp, ap);
        k_scatter<<<EB, 256>>>((const float4*)mp, row, col, ap);
        k_norm_hid<<<NB, 128>>>(hsrc, ap, hid_w + l * HID * HID,
                                conv_norm + l * HID, hid_norm + l * HID, hdst);
    }
}